// round 16
// baseline (speedup 1.0000x reference)
#include <cuda_runtime.h>
#include <cuda_fp16.h>
#include <cstdint>

// LuongAttention: O[b] = (Q Eᵀ) E == Q (EᵀE).  G = EᵀE per batch (128x128).
// R16: R15 (single-term fp16 HMMA, fp16 partials; err ~3.2e-4) with a finer
// ete pipeline — 4 stages of 32 tokens into one persistent smem plane, LDGs
// issued 2 stages ahead so loads fly under every MMA phase.  reduce is
// uint2-vectorized; qg hoists its first G-fragment loads above the Q store.

#define BB 8
#define NSPLIT 16
#define RSTRIDE 272                 // plane row stride, bytes
#define PLANE128 (128 * RSTRIDE)    // 34816 B: full 128-token hi plane
#define PLANE64  (64 * RSTRIDE)     // qg Q plane

// fp16 partials: [b][sp][row 128][d2 64] half2 words.
__device__ uint32_t g_parth[BB * NSPLIT * 128 * 64];   // 4 MB
// B-fragment layout: [b][n8tile 16][kstep 8][lane 32] = uint2 {hi_b0, hi_b1}.
__device__ uint2 g_frag[BB * 16 * 8 * 32];             // 256 KB

// ---------------- helpers ----------------
__device__ __forceinline__ uint32_t smem_u32(const void* p) {
    uint32_t a;
    asm("{ .reg .u64 t; cvta.to.shared.u64 t, %1; cvt.u32.u64 %0, t; }"
        : "=r"(a) : "l"(p));
    return a;
}
__device__ __forceinline__ void ldsm_x4(uint32_t (&r)[4], uint32_t addr) {
    asm volatile("ldmatrix.sync.aligned.m8n8.x4.shared.b16 {%0,%1,%2,%3}, [%4];"
                 : "=r"(r[0]), "=r"(r[1]), "=r"(r[2]), "=r"(r[3]) : "r"(addr));
}
__device__ __forceinline__ void ldsm_x4_t(uint32_t (&r)[4], uint32_t addr) {
    asm volatile("ldmatrix.sync.aligned.m8n8.x4.trans.shared.b16 {%0,%1,%2,%3}, [%4];"
                 : "=r"(r[0]), "=r"(r[1]), "=r"(r[2]), "=r"(r[3]) : "r"(addr));
}
__device__ __forceinline__ void mma16816(float (&d)[4], const uint32_t (&a)[4],
                                         uint32_t b0, uint32_t b1) {
    asm volatile(
        "mma.sync.aligned.m16n8k16.row.col.f32.f16.f16.f32 "
        "{%0,%1,%2,%3}, {%4,%5,%6,%7}, {%8,%9}, {%0,%1,%2,%3};"
        : "+f"(d[0]), "+f"(d[1]), "+f"(d[2]), "+f"(d[3])
        : "r"(a[0]), "r"(a[1]), "r"(a[2]), "r"(a[3]), "r"(b0), "r"(b1));
}
__device__ __forceinline__ uint32_t pack2h(float f0, float f1) {
    __half2 h = __floats2half2_rn(f0, f1);
    return *(uint32_t*)&h;
}

// ---------------------------------------------------------------------------
// Kernel 1: partial EᵀE.  CTA (sp, half): K = 128 tokens, 4 stages of 32
// tokens into ONE persistent smem plane (each stage owns its rows).
// Schedule per iter: store s+1 -> issue LDG s+3 -> MMA s -> sync.
// Grid (2*NSPLIT, BB); bx = sp*2 + half.
// ---------------------------------------------------------------------------
__global__ __launch_bounds__(256) void ete_hmma(const float* __restrict__ enc) {
    extern __shared__ char smem[];
    const uint32_t sb = smem_u32(smem);
    const int tid = threadIdx.x, wid = tid >> 5, lid = tid & 31;
    const int sp = blockIdx.x >> 1, half = blockIdx.x & 1, b = blockIdx.y;

    const float4* src =
        (const float4*)(enc + (size_t)(b * NSPLIT + sp) * (128 * 128));

    // Stage load (4 float4/thread) and convert/store helpers.
    float4 qA[4], qB[4];
#define LOADQ(dst, s)                                                          \
    do {                                                                       \
        _Pragma("unroll") for (int v = 0; v < 4; v++)                          \
            dst[v] = src[(s) * 1024 + tid + v * 256];                          \
    } while (0)
#define STOREQ(qr, s)                                                          \
    do {                                                                       \
        _Pragma("unroll") for (int v = 0; v < 4; v++) {                        \
            int idx = tid + v * 256;                                           \
            int t = (s) * 32 + (idx >> 5), d4 = idx & 31;                      \
            uint32_t off = (uint32_t)t * RSTRIDE + (uint32_t)d4 * 8;           \
            *(uint2*)(smem + off) =                                            \
                make_uint2(pack2h(qr[v].x, qr[v].y), pack2h(qr[v].z, qr[v].w)); \
        }                                                                      \
    } while (0)

    // MMA over one 32-token stage (2 ksteps), trans layout, 32x32 warp tile.
    const uint32_t aRow = (lid & 7) + ((lid >> 4) << 3);
    const uint32_t aCol = ((lid >> 3) & 1) << 3;
    const uint32_t bRow = (lid & 7) + (((lid >> 3) & 1) << 3);
    const uint32_t bCol = (lid >> 4) << 3;
    const int wm = half * 64 + (wid >> 2) * 32, wn = (wid & 3) * 32;

    float acc[2][4][4];
#pragma unroll
    for (int mi = 0; mi < 2; mi++)
#pragma unroll
        for (int nj = 0; nj < 4; nj++)
#pragma unroll
            for (int r = 0; r < 4; r++) acc[mi][nj][r] = 0.0f;

#define MMA_STAGE(s)                                                           \
    do {                                                                       \
        _Pragma("unroll") for (int kk = 2 * (s); kk < 2 * (s) + 2; kk++) {     \
            const int k0 = kk * 16;                                            \
            uint32_t Ah[2][4], Bh[2][4];                                       \
            _Pragma("unroll") for (int mi = 0; mi < 2; mi++) {                 \
                uint32_t off = (uint32_t)(k0 + aRow) * RSTRIDE +               \
                               (uint32_t)(wm + mi * 16 + aCol) * 2;            \
                ldsm_x4_t(Ah[mi], sb + off);                                   \
            }                                                                  \
            _Pragma("unroll") for (int np = 0; np < 2; np++) {                 \
                uint32_t off = (uint32_t)(k0 + bRow) * RSTRIDE +               \
                               (uint32_t)(wn + np * 16 + bCol) * 2;            \
                ldsm_x4_t(Bh[np], sb + off);                                   \
            }                                                                  \
            _Pragma("unroll") for (int mi = 0; mi < 2; mi++)                   \
                _Pragma("unroll") for (int nj = 0; nj < 4; nj++) {             \
                    const int np = nj >> 1, pr = (nj & 1) << 1;                \
                    mma16816(acc[mi][nj], Ah[mi], Bh[np][pr], Bh[np][pr + 1]); \
                }                                                              \
        }                                                                      \
    } while (0)

    // Prologue: stage0 load+store; stage1 load in flight.
    LOADQ(qA, 0);
    STOREQ(qA, 0);
    LOADQ(qB, 1);
    __syncthreads();

    // iter0: store s1, issue s2, MMA s0.
    STOREQ(qB, 1);
    LOADQ(qA, 2);
    MMA_STAGE(0);
    __syncthreads();

    // iter1: store s2, issue s3, MMA s1.
    STOREQ(qA, 2);
    LOADQ(qB, 3);
    MMA_STAGE(1);
    __syncthreads();

    // iter2: store s3, MMA s2.
    STOREQ(qB, 3);
    MMA_STAGE(2);
    __syncthreads();

    // iter3: MMA s3.
    MMA_STAGE(3);

    // Epilogue: fp16 half2 partial tile (C layout), bypassing L1.
    uint32_t* outp = g_parth + (((size_t)(b * NSPLIT + sp)) << 13);
    const int g = lid >> 2, tig = lid & 3;
#pragma unroll
    for (int mi = 0; mi < 2; mi++)
#pragma unroll
        for (int nj = 0; nj < 4; nj++) {
            const int row = wm + mi * 16 + g;
            const int d2 = (wn + nj * 8 + 2 * tig) >> 1;
            __stcg(outp + row * 64 + d2, pack2h(acc[mi][nj][0], acc[mi][nj][1]));
            __stcg(outp + (row + 8) * 64 + d2, pack2h(acc[mi][nj][2], acc[mi][nj][3]));
        }
#undef LOADQ
#undef STOREQ
#undef MMA_STAGE
}

// ---------------------------------------------------------------------------
// Kernel 2: reduce 16 fp16 partials (fp32 accum), uint2-vectorized; emit G
// rows as fp16 hi-only B-fragments.  Grid 128 x 256.
// ---------------------------------------------------------------------------
__global__ __launch_bounds__(256) void reduce_g() {
    const int e4 = blockIdx.x * 256 + threadIdx.x;  // 0..32767
    const int b = e4 >> 12;
    const int r = e4 & 4095;
    const int j = r >> 5, d4 = r & 31;              // d4 = pair of half2 words
    const uint2* base =
        (const uint2*)(g_parth + (((size_t)b * NSPLIT) << 13) + j * 64) + d4;
    float s0 = 0.f, s1 = 0.f, s2 = 0.f, s3 = 0.f;
#pragma unroll
    for (int sp = 0; sp < NSPLIT; sp++) {
        uint2 u = __ldcg(base + ((size_t)sp << 12));
        float2 va = __half22float2(*(__half2*)&u.x);
        float2 vb = __half22float2(*(__half2*)&u.y);
        s0 += va.x; s1 += va.y; s2 += vb.x; s3 += vb.y;
    }
    const int d2 = 2 * d4;                          // even
    const uint32_t lane = (uint32_t)(j & 7) * 4 + (d2 & 3);
    const uint32_t comp = (uint32_t)(d2 >> 2) & 1;
    const uint32_t slot =
        (((uint32_t)(b * 16 + (j >> 3)) * 8 + (d2 >> 3)) * 32 + lane);
    ((uint32_t*)g_frag)[slot * 2 + comp] = pack2h(s0, s1);
    ((uint32_t*)g_frag)[(slot + 1) * 2 + comp] = pack2h(s2, s3);
}

// ---------------------------------------------------------------------------
// Kernel 3: O_tile(64x128) = Qhi_tile @ Ghi.  Q hi plane in smem; G
// fragments (uint2) from gmem (L2-hot), first loads hoisted above Q store.
// ---------------------------------------------------------------------------
__global__ __launch_bounds__(256, 3) void qg_hmma(const float* __restrict__ dec,
                                                  float* __restrict__ out) {
    extern __shared__ char smem[];
    const uint32_t sb = smem_u32(smem);
    const int tid = threadIdx.x, wid = tid >> 5, lid = tid & 31;
    const int b = blockIdx.y, qt = blockIdx.x;

    const int wm = (wid >> 2) * 32, wn = (wid & 3) * 32;
    const uint2* gf = g_frag + ((size_t)(b * 16 + (wn >> 3)) * 8) * 32 + lid;

    const float4* qsrc = (const float4*)(dec + ((size_t)(b * 32 + qt) << 13));
    float4 q[8];
#pragma unroll
    for (int v = 0; v < 8; v++) q[v] = qsrc[tid + v * 256];

    // First two G-fragment batches fly under the Q split/store + sync.
    uint2 Gb[2][4];
#pragma unroll
    for (int nj = 0; nj < 4; nj++) Gb[0][nj] = gf[nj * 256];
#pragma unroll
    for (int nj = 0; nj < 4; nj++) Gb[1][nj] = gf[nj * 256 + 32];

#pragma unroll
    for (int v = 0; v < 8; v++) {
        int idx = tid + v * 256;
        int row = idx >> 5, d4 = idx & 31;
        uint32_t off = (uint32_t)row * RSTRIDE + (uint32_t)d4 * 8;
        *(uint2*)(smem + off) =
            make_uint2(pack2h(q[v].x, q[v].y), pack2h(q[v].z, q[v].w));
    }
    __syncthreads();

    float acc[2][4][4];
#pragma unroll
    for (int mi = 0; mi < 2; mi++)
#pragma unroll
        for (int nj = 0; nj < 4; nj++)
#pragma unroll
            for (int r = 0; r < 4; r++) acc[mi][nj][r] = 0.0f;

    const uint32_t aRow = lid & 15;
    const uint32_t aCol = (lid >> 4) << 3;

#pragma unroll
    for (int kk = 0; kk < 8; kk++) {
        const int k0 = kk * 16;
        const int buf = kk & 1;
        uint32_t Ah[2][4];
#pragma unroll
        for (int mi = 0; mi < 2; mi++) {
            uint32_t off = (uint32_t)(wm + mi * 16 + aRow) * RSTRIDE +
                           (uint32_t)(k0 + aCol) * 2;
            ldsm_x4(Ah[mi], sb + off);
        }
#pragma unroll
        for (int mi = 0; mi < 2; mi++)
#pragma unroll
            for (int nj = 0; nj < 4; nj++)
                mma16816(acc[mi][nj], Ah[mi], Gb[buf][nj].x, Gb[buf][nj].y);
        if (kk < 6) {
#pragma unroll
            for (int nj = 0; nj < 4; nj++)
                Gb[buf][nj] = gf[nj * 256 + (kk + 2) * 32];
        }
    }

    float* outp = out + ((size_t)(b * 32 + qt) << 13);
    const int g = lid >> 2, tig = lid & 3;
#pragma unroll
    for (int mi = 0; mi < 2; mi++)
#pragma unroll
        for (int nj = 0; nj < 4; nj++) {
            const int row = wm + mi * 16 + g;
            const int col = wn + nj * 8 + 2 * tig;
            *(float2*)(outp + row * 128 + col) =
                make_float2(acc[mi][nj][0], acc[mi][nj][1]);
            *(float2*)(outp + (row + 8) * 128 + col) =
                make_float2(acc[mi][nj][2], acc[mi][nj][3]);
        }
}

// ---------------------------------------------------------------------------
// Launch
// ---------------------------------------------------------------------------
extern "C" void kernel_launch(void* const* d_in, const int* in_sizes, int n_in,
                              void* d_out, int out_size) {
    const float* enc = (const float*)d_in[0];
    const float* dec = (const float*)d_in[1];
    float* out = (float*)d_out;

    cudaFuncSetAttribute(ete_hmma, cudaFuncAttributeMaxDynamicSharedMemorySize,
                         PLANE128);
    cudaFuncSetAttribute(qg_hmma, cudaFuncAttributeMaxDynamicSharedMemorySize,
                         PLANE64);

    ete_hmma<<<dim3(2 * NSPLIT, BB), 256, PLANE128>>>(enc);
    reduce_g<<<128, 256>>>();
    qg_hmma<<<dim3(32, BB), 256, PLANE64>>>(dec, out);
}

// round 17
// speedup vs baseline: 1.0216x; 1.0216x over previous
#include <cuda_runtime.h>
#include <cuda_fp16.h>
#include <cstdint>

// LuongAttention: O[b] = (Q Eᵀ) E == Q (EᵀE).  G = EᵀE per batch (128x128).
// R17: measured-best recombination.  ete = R15 2-stage double-buffer with the
// stage-1 LDG batch hoisted above the stage-0 store (more load flight time);
// reduce = R16 uint2-vectorized; qg = R16 hoisted G-prefetch + .cg stores.
// Single-term fp16 HMMA both GEMMs, fp16 partials (err ~3.2e-4 vs 1e-3 tol).

#define BB 8
#define NSPLIT 16
#define RSTRIDE 272                 // plane row stride, bytes
#define PLANE_T (64 * RSTRIDE)      // 17408 B (hi plane, 64 tokens)
#define STAGE_SZ PLANE_T            // one (hi-only) plane per stage

// fp16 partials: [b][sp][row 128][d2 64] half2 words.
__device__ uint32_t g_parth[BB * NSPLIT * 128 * 64];   // 4 MB
// B-fragment layout: [b][n8tile 16][kstep 8][lane 32] = uint2 {hi_b0, hi_b1}.
__device__ uint2 g_frag[BB * 16 * 8 * 32];             // 256 KB

// ---------------- helpers ----------------
__device__ __forceinline__ uint32_t smem_u32(const void* p) {
    uint32_t a;
    asm("{ .reg .u64 t; cvta.to.shared.u64 t, %1; cvt.u32.u64 %0, t; }"
        : "=r"(a) : "l"(p));
    return a;
}
__device__ __forceinline__ void ldsm_x4(uint32_t (&r)[4], uint32_t addr) {
    asm volatile("ldmatrix.sync.aligned.m8n8.x4.shared.b16 {%0,%1,%2,%3}, [%4];"
                 : "=r"(r[0]), "=r"(r[1]), "=r"(r[2]), "=r"(r[3]) : "r"(addr));
}
__device__ __forceinline__ void ldsm_x4_t(uint32_t (&r)[4], uint32_t addr) {
    asm volatile("ldmatrix.sync.aligned.m8n8.x4.trans.shared.b16 {%0,%1,%2,%3}, [%4];"
                 : "=r"(r[0]), "=r"(r[1]), "=r"(r[2]), "=r"(r[3]) : "r"(addr));
}
__device__ __forceinline__ void mma16816(float (&d)[4], const uint32_t (&a)[4],
                                         uint32_t b0, uint32_t b1) {
    asm volatile(
        "mma.sync.aligned.m16n8k16.row.col.f32.f16.f16.f32 "
        "{%0,%1,%2,%3}, {%4,%5,%6,%7}, {%8,%9}, {%0,%1,%2,%3};"
        : "+f"(d[0]), "+f"(d[1]), "+f"(d[2]), "+f"(d[3])
        : "r"(a[0]), "r"(a[1]), "r"(a[2]), "r"(a[3]), "r"(b0), "r"(b1));
}
__device__ __forceinline__ uint32_t pack2h(float f0, float f1) {
    __half2 h = __floats2half2_rn(f0, f1);
    return *(uint32_t*)&h;
}

// Convert+store one 64-token register batch into a stage's hi plane.
__device__ __forceinline__ void stage_store(char* smem, int stage, int tid,
                                            const float4* q) {
    char* base = smem + stage * STAGE_SZ;
#pragma unroll
    for (int v = 0; v < 8; v++) {
        int idx = tid + v * 256;
        int t = idx >> 5, d4 = idx & 31;
        uint32_t off = (uint32_t)t * RSTRIDE + (uint32_t)d4 * 8;
        *(uint2*)(base + off) =
            make_uint2(pack2h(q[v].x, q[v].y), pack2h(q[v].z, q[v].w));
    }
}

// MMA over one 64-token stage (4 ksteps), trans layout, 32x32 warp tile,
// single term (hi·hi).
__device__ __forceinline__ void stage_mma(uint32_t sbase, int wm, int wn, int lid,
                                          float (&acc)[2][4][4]) {
    const uint32_t aRow = (lid & 7) + ((lid >> 4) << 3);
    const uint32_t aCol = ((lid >> 3) & 1) << 3;
    const uint32_t bRow = (lid & 7) + (((lid >> 3) & 1) << 3);
    const uint32_t bCol = (lid >> 4) << 3;

#pragma unroll
    for (int kk = 0; kk < 4; kk++) {
        const int k0 = kk * 16;
        uint32_t Ah[2][4], Bh[2][4];
#pragma unroll
        for (int mi = 0; mi < 2; mi++) {
            uint32_t off = (uint32_t)(k0 + aRow) * RSTRIDE +
                           (uint32_t)(wm + mi * 16 + aCol) * 2;
            ldsm_x4_t(Ah[mi], sbase + off);
        }
#pragma unroll
        for (int np = 0; np < 2; np++) {
            uint32_t off = (uint32_t)(k0 + bRow) * RSTRIDE +
                           (uint32_t)(wn + np * 16 + bCol) * 2;
            ldsm_x4_t(Bh[np], sbase + off);
        }
#pragma unroll
        for (int mi = 0; mi < 2; mi++)
#pragma unroll
            for (int nj = 0; nj < 4; nj++) {
                const int np = nj >> 1, pr = (nj & 1) << 1;
                mma16816(acc[mi][nj], Ah[mi], Bh[np][pr], Bh[np][pr + 1]);
            }
    }
}

// ---------------------------------------------------------------------------
// Kernel 1: partial EᵀE.  CTA (sp, half): K = 128 tokens in two 64-token
// stages, double-buffered.  BOTH LDG batches are issued before the first
// store, so stage-1 loads fly under stage-0 convert/store/sync AND MMA.
// Epilogue: fp16 half2 partial tile, L1-bypass stores.
// ---------------------------------------------------------------------------
__global__ __launch_bounds__(256) void ete_hmma(const float* __restrict__ enc) {
    extern __shared__ char smem[];
    const uint32_t sb = smem_u32(smem);
    const int tid = threadIdx.x, wid = tid >> 5, lid = tid & 31;
    const int sp = blockIdx.x >> 1, half = blockIdx.x & 1, b = blockIdx.y;

    const float4* src =
        (const float4*)(enc + (size_t)(b * NSPLIT + sp) * (128 * 128));

    float4 q0[8], q1[8];
#pragma unroll
    for (int v = 0; v < 8; v++) q0[v] = src[tid + v * 256];
#pragma unroll
    for (int v = 0; v < 8; v++) q1[v] = src[2048 + tid + v * 256];

    stage_store(smem, 0, tid, q0);
    __syncthreads();

    const int wm = half * 64 + (wid >> 2) * 32, wn = (wid & 3) * 32;
    float acc[2][4][4];
#pragma unroll
    for (int mi = 0; mi < 2; mi++)
#pragma unroll
        for (int nj = 0; nj < 4; nj++)
#pragma unroll
            for (int r = 0; r < 4; r++) acc[mi][nj][r] = 0.0f;

    stage_mma(sb, wm, wn, lid, acc);            // tokens 0..63

    stage_store(smem, 1, tid, q1);
    __syncthreads();

    stage_mma(sb + STAGE_SZ, wm, wn, lid, acc); // tokens 64..127

    // Epilogue: fp16 half2 partial tile (C layout), bypassing L1.
    uint32_t* outp = g_parth + (((size_t)(b * NSPLIT + sp)) << 13);
    const int g = lid >> 2, tig = lid & 3;
#pragma unroll
    for (int mi = 0; mi < 2; mi++)
#pragma unroll
        for (int nj = 0; nj < 4; nj++) {
            const int row = wm + mi * 16 + g;
            const int d2 = (wn + nj * 8 + 2 * tig) >> 1;
            __stcg(outp + row * 64 + d2, pack2h(acc[mi][nj][0], acc[mi][nj][1]));
            __stcg(outp + (row + 8) * 64 + d2, pack2h(acc[mi][nj][2], acc[mi][nj][3]));
        }
}

// ---------------------------------------------------------------------------
// Kernel 2: reduce 16 fp16 partials (fp32 accum), uint2-vectorized; emit G
// rows as fp16 hi-only B-fragments.  Grid 128 x 256.
// ---------------------------------------------------------------------------
__global__ __launch_bounds__(256) void reduce_g() {
    const int e4 = blockIdx.x * 256 + threadIdx.x;  // 0..32767
    const int b = e4 >> 12;
    const int r = e4 & 4095;
    const int j = r >> 5, d4 = r & 31;              // d4 = pair of half2 words
    const uint2* base =
        (const uint2*)(g_parth + (((size_t)b * NSPLIT) << 13) + j * 64) + d4;
    float s0 = 0.f, s1 = 0.f, s2 = 0.f, s3 = 0.f;
#pragma unroll
    for (int sp = 0; sp < NSPLIT; sp++) {
        uint2 u = __ldcg(base + ((size_t)sp << 12));
        float2 va = __half22float2(*(__half2*)&u.x);
        float2 vb = __half22float2(*(__half2*)&u.y);
        s0 += va.x; s1 += va.y; s2 += vb.x; s3 += vb.y;
    }
    const int d2 = 2 * d4;                          // even
    const uint32_t lane = (uint32_t)(j & 7) * 4 + (d2 & 3);
    const uint32_t comp = (uint32_t)(d2 >> 2) & 1;
    const uint32_t slot =
        (((uint32_t)(b * 16 + (j >> 3)) * 8 + (d2 >> 3)) * 32 + lane);
    ((uint32_t*)g_frag)[slot * 2 + comp] = pack2h(s0, s1);
    ((uint32_t*)g_frag)[(slot + 1) * 2 + comp] = pack2h(s2, s3);
}

// ---------------------------------------------------------------------------
// Kernel 3: O_tile(64x128) = Qhi_tile @ Ghi.  Q hi plane in smem; G
// fragments (uint2) from gmem (L2-hot), first loads hoisted above Q store;
// output stores bypass L1 (.cg).
// ---------------------------------------------------------------------------
__global__ __launch_bounds__(256, 3) void qg_hmma(const float* __restrict__ dec,
                                                  float* __restrict__ out) {
    extern __shared__ char smem[];
    const uint32_t sb = smem_u32(smem);
    const int tid = threadIdx.x, wid = tid >> 5, lid = tid & 31;
    const int b = blockIdx.y, qt = blockIdx.x;

    const int wm = (wid >> 2) * 32, wn = (wid & 3) * 32;
    const uint2* gf = g_frag + ((size_t)(b * 16 + (wn >> 3)) * 8) * 32 + lid;

    const float4* qsrc = (const float4*)(dec + ((size_t)(b * 32 + qt) << 13));
    float4 q[8];
#pragma unroll
    for (int v = 0; v < 8; v++) q[v] = qsrc[tid + v * 256];

    // First two G-fragment batches fly under the Q split/store + sync.
    uint2 Gb[2][4];
#pragma unroll
    for (int nj = 0; nj < 4; nj++) Gb[0][nj] = gf[nj * 256];
#pragma unroll
    for (int nj = 0; nj < 4; nj++) Gb[1][nj] = gf[nj * 256 + 32];

#pragma unroll
    for (int v = 0; v < 8; v++) {
        int idx = tid + v * 256;
        int row = idx >> 5, d4 = idx & 31;
        uint32_t off = (uint32_t)row * RSTRIDE + (uint32_t)d4 * 8;
        *(uint2*)(smem + off) =
            make_uint2(pack2h(q[v].x, q[v].y), pack2h(q[v].z, q[v].w));
    }
    __syncthreads();

    float acc[2][4][4];
#pragma unroll
    for (int mi = 0; mi < 2; mi++)
#pragma unroll
        for (int nj = 0; nj < 4; nj++)
#pragma unroll
            for (int r = 0; r < 4; r++) acc[mi][nj][r] = 0.0f;

    const uint32_t aRow = lid & 15;
    const uint32_t aCol = (lid >> 4) << 3;

#pragma unroll
    for (int kk = 0; kk < 8; kk++) {
        const int k0 = kk * 16;
        const int buf = kk & 1;
        uint32_t Ah[2][4];
#pragma unroll
        for (int mi = 0; mi < 2; mi++) {
            uint32_t off = (uint32_t)(wm + mi * 16 + aRow) * RSTRIDE +
                           (uint32_t)(k0 + aCol) * 2;
            ldsm_x4(Ah[mi], sb + off);
        }
#pragma unroll
        for (int mi = 0; mi < 2; mi++)
#pragma unroll
            for (int nj = 0; nj < 4; nj++)
                mma16816(acc[mi][nj], Ah[mi], Gb[buf][nj].x, Gb[buf][nj].y);
        if (kk < 6) {
#pragma unroll
            for (int nj = 0; nj < 4; nj++)
                Gb[buf][nj] = gf[nj * 256 + (kk + 2) * 32];
        }
    }

    float* outp = out + ((size_t)(b * 32 + qt) << 13);
    const int g = lid >> 2, tig = lid & 3;
#pragma unroll
    for (int mi = 0; mi < 2; mi++)
#pragma unroll
        for (int nj = 0; nj < 4; nj++) {
            const int row = wm + mi * 16 + g;
            const int col = wn + nj * 8 + 2 * tig;
            __stcg((float2*)(outp + row * 128 + col),
                   make_float2(acc[mi][nj][0], acc[mi][nj][1]));
            __stcg((float2*)(outp + (row + 8) * 128 + col),
                   make_float2(acc[mi][nj][2], acc[mi][nj][3]));
        }
}

// ---------------------------------------------------------------------------
// Launch
// ---------------------------------------------------------------------------
extern "C" void kernel_launch(void* const* d_in, const int* in_sizes, int n_in,
                              void* d_out, int out_size) {
    const float* enc = (const float*)d_in[0];
    const float* dec = (const float*)d_in[1];
    float* out = (float*)d_out;

    cudaFuncSetAttribute(ete_hmma, cudaFuncAttributeMaxDynamicSharedMemorySize,
                         2 * STAGE_SZ);
    cudaFuncSetAttribute(qg_hmma, cudaFuncAttributeMaxDynamicSharedMemorySize,
                         PLANE_T);

    ete_hmma<<<dim3(2 * NSPLIT, BB), 256, 2 * STAGE_SZ>>>(enc);
    reduce_g<<<128, 256>>>();
    qg_hmma<<<dim3(32, BB), 256, PLANE_T>>>(dec, out);
}